// round 8
// baseline (speedup 1.0000x reference)
#include <cuda_runtime.h>

// ObservabilityWeightedMSE — fused single-launch weighted-MSE reduction.
// d_in[0]=predictions [500000,82] f32, d_in[1]=targets [500000,82] f32,
// d_in[2]=inputs [500000,400] f32. Output: scalar f32.
// R3: occupancy-bound at >32 regs -> __launch_bounds__(256,8).
// R5: __threadfence per block (CCTL.IVALL) -> +16us.
// R7: atom.acq_rel per block (acquire = L1 invalidate) -> +12us.
// R8: release-ONLY arrival per block (no L1 invalidate); the single last
//     block does ONE acq_rel fence before reading partials.

#define THRESH   1e-4f
#define NCOLS    82
#define ROW_IN   400
#define NBLOCKS  1184
#define NTHREADS 256

__device__ float        g_part[NBLOCKS];
__device__ unsigned int g_count = 0;   // self-resetting each call

__device__ __forceinline__ unsigned atom_inc_release(unsigned int* p) {
    unsigned old;
    asm volatile("atom.release.gpu.global.add.u32 %0, [%1], 1;"
                 : "=r"(old) : "l"(p) : "memory");
    return old;
}

__global__ void __launch_bounds__(NTHREADS, 8)   // cap regs at 32: 8 blocks/SM
wmse_kernel(const float* __restrict__ pred,
            const float* __restrict__ targ,
            const float* __restrict__ inp,
            int B, double inv_total, float* __restrict__ out)
{
    const int lane  = threadIdx.x & 31;
    const int warp  = threadIdx.x >> 5;
    const int gwarp = blockIdx.x * (NTHREADS / 32) + warp;
    const int nwarp = NBLOCKS * (NTHREADS / 32);

    // lane-constant geometry for the inputs magnitude slice
    const int  n0   = lane / 5, p0 = lane % 5;      // float4 idx = lane
    const int  i1   = 32 + lane;
    const int  n1   = i1 / 5,  p1 = i1 % 5;         // float4 idx = 32+lane
    const bool has1 = (i1 < 50);                    // lanes 0..17
    const int  off0 = n0 * 40 + p0 * 4;
    const int  off1 = n1 * 40 + p1 * 4;

    float acc = 0.0f;

    for (int r = gwarp; r < B; r += nwarp) {
        const float* pin = inp + (size_t)r * ROW_IN;

        // ---- node-below test: below[n] <=> max of 20 magnitudes < THRESH ----
        float4 a0 = *(const float4*)(pin + off0);
        unsigned ok = 0;
        if (fmaxf(fmaxf(a0.x, a0.y), fmaxf(a0.z, a0.w)) >= THRESH)
            ok = 1u << n0;
        if (has1) {
            float4 a1 = *(const float4*)(pin + off1);
            if (fmaxf(fmaxf(a1.x, a1.y), fmaxf(a1.z, a1.w)) >= THRESH)
                ok |= 1u << n1;
        }
        unsigned below = (~__reduce_or_sync(0xffffffffu, ok)) & 0x3FFu;
        const int cut = below ? (__ffs(below) << 2) : 1000;

        // ---- weighted MSE over 82 columns, coalesced scalar loads ----
        const float* pp = pred + (size_t)r * NCOLS;
        const float* pt = targ + (size_t)r * NCOLS;
        #pragma unroll
        for (int it = 0; it < 3; ++it) {
            int c = it * 32 + lane;
            if (c < NCOLS) {
                float d = pp[c] - pt[c];
                bool five; int col;
                if (c < 41) { col = c; five = ((c & 3) == 0); }
                else {
                    int j = c - 41; col = j;
                    five = ((j & 3) == 3) || (((j & 3) == 0) && (j != 40));
                }
                float w = five ? 5.0f : 1.0f;
                if (col >= cut) w *= 0.1f;
                acc = fmaf(d * d, w, acc);
            }
        }
    }

    // ---- block reduction -> partial store + release-only arrival ----
    #pragma unroll
    for (int o = 16; o > 0; o >>= 1)
        acc += __shfl_down_sync(0xffffffffu, acc, o);

    __shared__ float smem[NTHREADS / 32];
    __shared__ bool  s_last;
    if (lane == 0) smem[warp] = acc;
    __syncthreads();
    if (warp == 0) {
        float v = (lane < (NTHREADS / 32)) ? smem[lane] : 0.0f;
        #pragma unroll
        for (int o = 4; o > 0; o >>= 1)
            v += __shfl_down_sync(0xffffffffu, v, o);
        if (lane == 0) {
            g_part[blockIdx.x] = v;                 // write-through to L2
            // release-only: orders the STG above at gpu scope, NO L1 flush.
            unsigned n = atom_inc_release(&g_count);
            s_last = (n == NBLOCKS - 1);
        }
    }
    __syncthreads();

    // ---- last block only: one acquire fence, then deterministic reduce ----
    if (s_last) {
        asm volatile("fence.acq_rel.gpu;" ::: "memory");  // single CCTL.IVALL
        double a = 0.0;
        for (int i = threadIdx.x; i < NBLOCKS; i += NTHREADS)
            a += (double)__ldcg(&g_part[i]);
        #pragma unroll
        for (int o = 16; o > 0; o >>= 1)
            a += __shfl_down_sync(0xffffffffu, a, o);
        __shared__ double sd[NTHREADS / 32];
        if (lane == 0) sd[warp] = a;
        __syncthreads();
        if (warp == 0) {
            a = (lane < (NTHREADS / 32)) ? sd[lane] : 0.0;
            #pragma unroll
            for (int o = 4; o > 0; o >>= 1)
                a += __shfl_down_sync(0xffffffffu, a, o);
            if (lane == 0) {
                out[0]  = (float)(a * inv_total);
                g_count = 0;                        // reset for next replay
            }
        }
    }
}

extern "C" void kernel_launch(void* const* d_in, const int* in_sizes, int n_in,
                              void* d_out, int out_size)
{
    const float* pred = (const float*)d_in[0];
    const float* targ = (const float*)d_in[1];
    const float* inp  = (const float*)d_in[2];
    float* out = (float*)d_out;

    const int B = in_sizes[0] / NCOLS;   // 500000

    wmse_kernel<<<NBLOCKS, NTHREADS>>>(pred, targ, inp, B,
                                       1.0 / ((double)B * NCOLS), out);
}

// round 9
// speedup vs baseline: 1.0874x; 1.0874x over previous
#include <cuda_runtime.h>

// ObservabilityWeightedMSE — weighted-MSE reduction, two launches.
// d_in[0]=predictions [500000,82] f32, d_in[1]=targets [500000,82] f32,
// d_in[2]=inputs [500000,400] f32. Output: scalar f32.
//
// Locked-in experimental facts:
//  R3: >32 regs costs occupancy -> __launch_bounds__(256,8).
//  R4/R5: __ldcs evict-first and occupancy were not the issue.
//  R5/R7/R8: ANY fused last-block tail (fence / acq_rel / release-only)
//            costs ~15us vs two-launch. Two-launch is the winning family.
//  Body is at ~89% HBM (1.128 GB granule-floor traffic) — memory wall.
// R9: shave the only remaining overhead: finalize -> single warp, no syncs.

#define THRESH   1e-4f
#define NCOLS    82
#define ROW_IN   400
#define NBLOCKS  1184
#define NTHREADS 256

__device__ double g_part[NBLOCKS];

__global__ void __launch_bounds__(NTHREADS, 8)   // cap regs at 32: 8 blocks/SM
wmse_kernel(const float* __restrict__ pred,
            const float* __restrict__ targ,
            const float* __restrict__ inp,
            int B)
{
    const int lane  = threadIdx.x & 31;
    const int warp  = threadIdx.x >> 5;
    const int gwarp = blockIdx.x * (NTHREADS / 32) + warp;
    const int nwarp = NBLOCKS * (NTHREADS / 32);

    // lane-constant geometry for the inputs magnitude slice
    const int  n0   = lane / 5, p0 = lane % 5;      // float4 idx = lane
    const int  i1   = 32 + lane;
    const int  n1   = i1 / 5,  p1 = i1 % 5;         // float4 idx = 32+lane
    const bool has1 = (i1 < 50);                    // lanes 0..17
    const int  off0 = n0 * 40 + p0 * 4;
    const int  off1 = n1 * 40 + p1 * 4;

    float acc = 0.0f;

    for (int r = gwarp; r < B; r += nwarp) {
        const float* pin = inp + (size_t)r * ROW_IN;

        // ---- node-below test: below[n] <=> max of 20 magnitudes < THRESH ----
        float4 a0 = *(const float4*)(pin + off0);
        unsigned ok = 0;
        if (fmaxf(fmaxf(a0.x, a0.y), fmaxf(a0.z, a0.w)) >= THRESH)
            ok = 1u << n0;
        if (has1) {
            float4 a1 = *(const float4*)(pin + off1);
            if (fmaxf(fmaxf(a1.x, a1.y), fmaxf(a1.z, a1.w)) >= THRESH)
                ok |= 1u << n1;
        }
        unsigned below = (~__reduce_or_sync(0xffffffffu, ok)) & 0x3FFu;
        const int cut = below ? (__ffs(below) << 2) : 1000;

        // ---- weighted MSE over 82 columns, coalesced scalar loads ----
        const float* pp = pred + (size_t)r * NCOLS;
        const float* pt = targ + (size_t)r * NCOLS;
        #pragma unroll
        for (int it = 0; it < 3; ++it) {
            int c = it * 32 + lane;
            if (c < NCOLS) {
                float d = pp[c] - pt[c];
                bool five; int col;
                if (c < 41) { col = c; five = ((c & 3) == 0); }
                else {
                    int j = c - 41; col = j;
                    five = ((j & 3) == 3) || (((j & 3) == 0) && (j != 40));
                }
                float w = five ? 5.0f : 1.0f;
                if (col >= cut) w *= 0.1f;
                acc = fmaf(d * d, w, acc);
            }
        }
    }

    // ---- block reduction -> one plain store per block ----
    #pragma unroll
    for (int o = 16; o > 0; o >>= 1)
        acc += __shfl_down_sync(0xffffffffu, acc, o);

    __shared__ float smem[NTHREADS / 32];
    if (lane == 0) smem[warp] = acc;
    __syncthreads();
    if (warp == 0) {
        float v = (lane < (NTHREADS / 32)) ? smem[lane] : 0.0f;
        #pragma unroll
        for (int o = 4; o > 0; o >>= 1)
            v += __shfl_down_sync(0xffffffffu, v, o);
        if (lane == 0) g_part[blockIdx.x] = (double)v;
    }
}

// Single-warp finalize: no shared memory, no __syncthreads, minimal launch cost.
__global__ void __launch_bounds__(32)
finalize_kernel(float* __restrict__ out, double inv_total)
{
    const int lane = threadIdx.x;
    double a = 0.0;
    #pragma unroll 4
    for (int i = lane; i < NBLOCKS; i += 32)
        a += g_part[i];
    #pragma unroll
    for (int o = 16; o > 0; o >>= 1)
        a += __shfl_down_sync(0xffffffffu, a, o);
    if (lane == 0) out[0] = (float)(a * inv_total);
}

extern "C" void kernel_launch(void* const* d_in, const int* in_sizes, int n_in,
                              void* d_out, int out_size)
{
    const float* pred = (const float*)d_in[0];
    const float* targ = (const float*)d_in[1];
    const float* inp  = (const float*)d_in[2];
    float* out = (float*)d_out;

    const int B = in_sizes[0] / NCOLS;   // 500000

    wmse_kernel<<<NBLOCKS, NTHREADS>>>(pred, targ, inp, B);
    finalize_kernel<<<1, 32>>>(out, 1.0 / ((double)B * NCOLS));
}

// round 10
// speedup vs baseline: 1.1175x; 1.0277x over previous
#include <cuda_runtime.h>

// ObservabilityWeightedMSE — weighted-MSE reduction, two launches.
// d_in[0]=predictions [500000,82] f32, d_in[1]=targets [500000,82] f32,
// d_in[2]=inputs [500000,400] f32. Output: scalar f32.
//
// Locked-in experimental facts:
//  R3: >32 regs costs occupancy -> __launch_bounds__(256,8).
//  R5/R7/R8: ANY fused last-block tail costs ~15us vs two-launch.
//  R9: finalize is LATENCY-bound (32-thread version slower than 1024).
//  Body sits at the ~1.13GB DRAM-granule floor (~79% DRAM) — memory wall.
// R10: blocks atomicAdd(double) into one accumulator (cheap, no waiting);
//      finalize collapses to <<<1,1>>> read+scale+reset (~3.5us).

#define THRESH   1e-4f
#define NCOLS    82
#define ROW_IN   400
#define NBLOCKS  1184
#define NTHREADS 256

__device__ double g_acc = 0.0;   // reset by finalize after each use

__global__ void __launch_bounds__(NTHREADS, 8)   // cap regs at 32: 8 blocks/SM
wmse_kernel(const float* __restrict__ pred,
            const float* __restrict__ targ,
            const float* __restrict__ inp,
            int B)
{
    const int lane  = threadIdx.x & 31;
    const int warp  = threadIdx.x >> 5;
    const int gwarp = blockIdx.x * (NTHREADS / 32) + warp;
    const int nwarp = NBLOCKS * (NTHREADS / 32);

    // lane-constant geometry for the inputs magnitude slice
    const int  n0   = lane / 5, p0 = lane % 5;      // float4 idx = lane
    const int  i1   = 32 + lane;
    const int  n1   = i1 / 5,  p1 = i1 % 5;         // float4 idx = 32+lane
    const bool has1 = (i1 < 50);                    // lanes 0..17
    const int  off0 = n0 * 40 + p0 * 4;
    const int  off1 = n1 * 40 + p1 * 4;

    float acc = 0.0f;

    for (int r = gwarp; r < B; r += nwarp) {
        const float* pin = inp + (size_t)r * ROW_IN;

        // ---- node-below test: below[n] <=> max of 20 magnitudes < THRESH ----
        float4 a0 = *(const float4*)(pin + off0);
        unsigned ok = 0;
        if (fmaxf(fmaxf(a0.x, a0.y), fmaxf(a0.z, a0.w)) >= THRESH)
            ok = 1u << n0;
        if (has1) {
            float4 a1 = *(const float4*)(pin + off1);
            if (fmaxf(fmaxf(a1.x, a1.y), fmaxf(a1.z, a1.w)) >= THRESH)
                ok |= 1u << n1;
        }
        unsigned below = (~__reduce_or_sync(0xffffffffu, ok)) & 0x3FFu;
        // below==0 -> ffs(0x400)=11 -> cut=44 > max col 40 -> never cuts
        const int cut = __ffs(below | 0x400u) << 2;

        // ---- weighted MSE over 82 columns, coalesced scalar loads ----
        const float* pp = pred + (size_t)r * NCOLS;
        const float* pt = targ + (size_t)r * NCOLS;
        #pragma unroll
        for (int it = 0; it < 3; ++it) {
            int c = it * 32 + lane;
            if (c < NCOLS) {
                float d = pp[c] - pt[c];
                bool five; int col;
                if (c < 41) { col = c; five = ((c & 3) == 0); }
                else {
                    int j = c - 41; col = j;
                    five = ((j & 3) == 3) || (((j & 3) == 0) && (j != 40));
                }
                float w = five ? 5.0f : 1.0f;
                if (col >= cut) w *= 0.1f;
                acc = fmaf(d * d, w, acc);
            }
        }
    }

    // ---- block reduction -> one double atomic per block ----
    #pragma unroll
    for (int o = 16; o > 0; o >>= 1)
        acc += __shfl_down_sync(0xffffffffu, acc, o);

    __shared__ float smem[NTHREADS / 32];
    if (lane == 0) smem[warp] = acc;
    __syncthreads();
    if (warp == 0) {
        float v = (lane < (NTHREADS / 32)) ? smem[lane] : 0.0f;
        #pragma unroll
        for (int o = 4; o > 0; o >>= 1)
            v += __shfl_down_sync(0xffffffffu, v, o);
        if (lane == 0) atomicAdd(&g_acc, (double)v);
    }
}

// Minimal finalize: read accumulator, scale, write output, reset for next replay.
__global__ void finalize_kernel(float* __restrict__ out, double inv_total)
{
    out[0] = (float)(g_acc * inv_total);
    g_acc  = 0.0;
}

extern "C" void kernel_launch(void* const* d_in, const int* in_sizes, int n_in,
                              void* d_out, int out_size)
{
    const float* pred = (const float*)d_in[0];
    const float* targ = (const float*)d_in[1];
    const float* inp  = (const float*)d_in[2];
    float* out = (float*)d_out;

    const int B = in_sizes[0] / NCOLS;   // 500000

    wmse_kernel<<<NBLOCKS, NTHREADS>>>(pred, targ, inp, B);
    finalize_kernel<<<1, 1>>>(out, 1.0 / ((double)B * NCOLS));
}